// round 7
// baseline (speedup 1.0000x reference)
#include <cuda_runtime.h>
#include <cuda_bf16.h>
#include <cstdint>
#include <cstddef>

// Problem dims (fixed)
#define T_STEPS 100
#define BATCH   256
#define IN_DIM  784
#define HID     1024
#define OUT_DIM 10
#define MROWS   25600
#define BH      262144
#define BO      2560
#define HID_OUT ((size_t)MROWS * HID)
#define THRESH 0.9f
#define DECAY  0.6f

// GEMM1 tiling: 128x128 CTA tile, BK=16 slabs, K padded to 800 -> 50 slabs,
// 25 barrier iterations (2 slabs per wait+sync), 6-stage cp.async ring.
#define KPAD 800
#define NSLAB 50
#define NITER 25
#define NSTAGE 6
#define A_STAGE_B 6144u     // 128 rows * 48B (16 bf16 padded to 24)
#define B_PLANE_B 4352u     // 16 rows * 272B (128 bf16 padded to 136)
#define STAGE_B  14848u     // A + 2 B planes
#define SMEM_TOTAL (NSTAGE * STAGE_B)   // 89088 -> 2 CTAs/SM
#define WELEM ((size_t)KPAD * HID)      // 819200 per W plane

// ------------------------- scratch (device globals) -----------------------
__device__ __nv_bfloat16 g_Xbf[(size_t)MROWS * KPAD];   // 41.0 MB, K-padded
__device__ __nv_bfloat16 g_W1c[2 * WELEM];              // hi plane | lo plane, [800][1024]
__device__ float         g_U1[(size_t)MROWS * HID];     // 104.9 MB
__device__ float         g_U2[(size_t)MROWS * OUT_DIM]; // 1.0 MB

// ------------------------- helpers ---------------------------------------
__device__ __forceinline__ uint32_t smem_u32(const void* p) {
    uint32_t a;
    asm("{ .reg .u64 t; cvta.to.shared.u64 t, %1; cvt.u32.u64 %0, t; }" : "=r"(a) : "l"(p));
    return a;
}
__device__ __forceinline__ void cpa16(uint32_t s, const void* g) {
    asm volatile("cp.async.cg.shared.global [%0], [%1], 16;\n" :: "r"(s), "l"(g));
}
__device__ __forceinline__ void ldsm_x4(uint32_t& r0, uint32_t& r1, uint32_t& r2, uint32_t& r3, uint32_t addr) {
    asm volatile("ldmatrix.sync.aligned.m8n8.x4.shared.b16 {%0,%1,%2,%3}, [%4];\n"
                 : "=r"(r0), "=r"(r1), "=r"(r2), "=r"(r3) : "r"(addr));
}
__device__ __forceinline__ void ldsm_x4_t(uint32_t& r0, uint32_t& r1, uint32_t& r2, uint32_t& r3, uint32_t addr) {
    asm volatile("ldmatrix.sync.aligned.m8n8.x4.trans.shared.b16 {%0,%1,%2,%3}, [%4];\n"
                 : "=r"(r0), "=r"(r1), "=r"(r2), "=r"(r3) : "r"(addr));
}
__device__ __forceinline__ void mma16816(float* c, const uint32_t* a, uint32_t b0, uint32_t b1) {
    asm volatile(
        "mma.sync.aligned.m16n8k16.row.col.f32.bf16.bf16.f32 "
        "{%0,%1,%2,%3}, {%4,%5,%6,%7}, {%8,%9}, {%0,%1,%2,%3};\n"
        : "+f"(c[0]), "+f"(c[1]), "+f"(c[2]), "+f"(c[3])
        : "r"(a[0]), "r"(a[1]), "r"(a[2]), "r"(a[3]), "r"(b0), "r"(b1));
}

// ------------------------- fused prep kernel -------------------------------
// Blocks [0, 10000): X fp32 -> bf16 K-padded [25600][800]
// Blocks [10000, 13200): W1 -> split hi/lo bf16 planes [800][1024]
// Blocks [13200, 13450): zero U2
#define PREPX_BLKS 10000
#define PREPW_BLKS 3200
#define ZERO_BLKS  250
__global__ void prep_kernel(const float* __restrict__ x, const float* __restrict__ w1) {
    const int bid = blockIdx.x;
    if (bid < PREPX_BLKS) {
        int i = bid * 256 + threadIdx.x;                  // < 2,560,000 (16B chunks)
        int row = i / 100, c8 = i % 100;
        uint4 o;
        if (c8 < 98) {
            const float4* src = (const float4*)(x + (size_t)row * IN_DIM + c8 * 8);
            float4 a = src[0], b = src[1];
            __nv_bfloat162 h0 = __floats2bfloat162_rn(a.x, a.y);
            __nv_bfloat162 h1 = __floats2bfloat162_rn(a.z, a.w);
            __nv_bfloat162 h2 = __floats2bfloat162_rn(b.x, b.y);
            __nv_bfloat162 h3 = __floats2bfloat162_rn(b.z, b.w);
            o.x = *reinterpret_cast<uint32_t*>(&h0);
            o.y = *reinterpret_cast<uint32_t*>(&h1);
            o.z = *reinterpret_cast<uint32_t*>(&h2);
            o.w = *reinterpret_cast<uint32_t*>(&h3);
        } else {
            o = make_uint4(0, 0, 0, 0);
        }
        *reinterpret_cast<uint4*>(g_Xbf + (size_t)row * KPAD + c8 * 8) = o;
    } else if (bid < PREPX_BLKS + PREPW_BLKS) {
        int i = (bid - PREPX_BLKS) * 256 + threadIdx.x;   // < 819200
        int k = i >> 10, n = i & 1023;
        float w = (k < IN_DIM) ? w1[(size_t)k * HID + n] : 0.0f;
        __nv_bfloat16 hi = __float2bfloat16(w);
        __nv_bfloat16 lo = __float2bfloat16(w - __bfloat162float(hi));
        g_W1c[i] = hi;
        g_W1c[WELEM + i] = lo;
    } else {
        int i = (bid - PREPX_BLKS - PREPW_BLKS) * 256 + threadIdx.x;  // < 64000
        reinterpret_cast<float4*>(g_U2)[i] = make_float4(0.f, 0.f, 0.f, 0.f);
    }
}

// ------------------------- GEMM1: U1 = X @ (W1hi + W1lo) ------------------
// 8 warps (2x4), warp tile 64x32, fp32 accum; hi/lo passes share the A tile.
// Two BK=16 slabs per barrier iteration.
__global__ __launch_bounds__(256, 2) void gemm1_kernel() {
    extern __shared__ char smem[];
    const uint32_t sbase = smem_u32(smem);

    const int tid = threadIdx.x;
    const int bn0 = blockIdx.x * 128;
    const int bm0 = blockIdx.y * 128;

    const int lane   = tid & 31;
    const int wid    = tid >> 5;
    const int warp_m = wid >> 2;   // 0..1
    const int warp_n = wid & 3;    // 0..3

    float acc[4][4][4];
#pragma unroll
    for (int i = 0; i < 4; i++)
#pragma unroll
        for (int j = 0; j < 4; j++)
#pragma unroll
            for (int k = 0; k < 4; k++) acc[i][j][k] = 0.0f;

    // producer addressing
    const int arow = tid >> 1, ach = tid & 1;
    const __nv_bfloat16* agp = g_Xbf + (size_t)(bm0 + arow) * KPAD + ach * 8;
    const int brow = tid >> 4, bch = tid & 15;
    const __nv_bfloat16* bgp = g_W1c + (size_t)brow * HID + bn0 + bch * 8;

    const uint32_t a_dst = sbase + arow * 48 + ach * 16;
    const uint32_t b_dst = sbase + A_STAGE_B + brow * 272 + bch * 16;

#define LOAD_STAGE(slot, kt) do {                                                   \
        uint32_t so = (slot) * STAGE_B;                                             \
        const __nv_bfloat16* a = agp + (size_t)(kt) * 16;                           \
        const __nv_bfloat16* b = bgp + (size_t)(kt) * 16 * HID;                     \
        cpa16(a_dst + so, a);                                                       \
        cpa16(b_dst + so, b);                                                       \
        cpa16(b_dst + so + B_PLANE_B, b + WELEM);                                   \
        asm volatile("cp.async.commit_group;\n" ::: "memory");                      \
    } while (0)

#define COMPUTE_SLAB(slot) do {                                                     \
        const uint32_t so = sbase + (slot) * STAGE_B;                               \
        uint32_t a[4][4];                                                           \
        _Pragma("unroll")                                                           \
        for (int mt = 0; mt < 4; mt++) {                                            \
            int row = warp_m * 64 + mt * 16 + (lane & 15);                          \
            uint32_t addr = so + row * 48 + (lane >> 4) * 16;                       \
            ldsm_x4(a[mt][0], a[mt][1], a[mt][2], a[mt][3], addr);                  \
        }                                                                           \
        _Pragma("unroll")                                                           \
        for (int p = 0; p < 2; p++) {                                               \
            _Pragma("unroll")                                                       \
            for (int nt = 0; nt < 2; nt++) {                                        \
                uint32_t b0, b1, b2, b3;                                            \
                int krow = lane & 15;                                               \
                int col  = warp_n * 32 + nt * 16 + (lane >> 4) * 8;                 \
                uint32_t addr = so + A_STAGE_B + p * B_PLANE_B + krow * 272 + col * 2; \
                ldsm_x4_t(b0, b1, b2, b3, addr);                                    \
                _Pragma("unroll")                                                   \
                for (int mt = 0; mt < 4; mt++) {                                    \
                    mma16816(acc[mt][nt * 2],     a[mt], b0, b1);                   \
                    mma16816(acc[mt][nt * 2 + 1], a[mt], b2, b3);                   \
                }                                                                   \
            }                                                                       \
        }                                                                           \
    } while (0)

    LOAD_STAGE(0, 0);
    LOAD_STAGE(1, 1);
    LOAD_STAGE(2, 2);
    LOAD_STAGE(3, 3);

    int cslot = 0;   // slot of first compute slab this iter
    int pslot = 4;   // slot receiving prefetch this iter
    for (int it = 0; it < NITER; it++) {
        asm volatile("cp.async.wait_group 2;\n" ::: "memory");
        __syncthreads();

        const int kt = 2 * it + 4;   // prefetch slab index (and kt+1)
        if (kt < NSLAB) {
            LOAD_STAGE(pslot, kt);
            int p2 = pslot + 1; if (p2 == NSTAGE) p2 = 0;
            if (kt + 1 < NSLAB) {
                LOAD_STAGE(p2, kt + 1);
            } else {
                asm volatile("cp.async.commit_group;\n" ::: "memory");
            }
        } else {
            asm volatile("cp.async.commit_group;\n" ::: "memory");
            asm volatile("cp.async.commit_group;\n" ::: "memory");
        }

        COMPUTE_SLAB(cslot);
        int c2 = cslot + 1; if (c2 == NSTAGE) c2 = 0;
        COMPUTE_SLAB(c2);

        cslot += 2; if (cslot >= NSTAGE) cslot -= NSTAGE;
        pslot += 2; if (pslot >= NSTAGE) pslot -= NSTAGE;
    }
#undef LOAD_STAGE
#undef COMPUTE_SLAB

    // epilogue: write U1 (fp32)
    const int g  = lane >> 2;
    const int tg = lane & 3;
#pragma unroll
    for (int mt = 0; mt < 4; mt++) {
        int m0 = bm0 + warp_m * 64 + mt * 16 + g;
#pragma unroll
        for (int nf = 0; nf < 4; nf++) {
            int n0 = bn0 + warp_n * 32 + nf * 8 + tg * 2;
            float2 v0 = make_float2(acc[mt][nf][0], acc[mt][nf][1]);
            float2 v1 = make_float2(acc[mt][nf][2], acc[mt][nf][3]);
            *(float2*)&g_U1[(size_t)m0 * HID + n0]       = v0;
            *(float2*)&g_U1[(size_t)(m0 + 8) * HID + n0] = v1;
        }
    }
}

// ---------------- scan1: LIF hidden + fused sparse GEMM2 ------------------
__global__ void scan1_kernel(float4* __restrict__ out, const float* __restrict__ W2) {
    const int idx = blockIdx.x * blockDim.x + threadIdx.x;   // 0..65535
    const float4* u = reinterpret_cast<const float4*>(g_U1);
    const int j0 = idx * 4;
    const int b  = j0 >> 10;
    const int h0 = j0 & 1023;
    float4 mem = make_float4(0.f, 0.f, 0.f, 0.f);
#pragma unroll 4
    for (int t = 0; t < T_STEPS; t++) {
        float4 v = __ldcg(&u[(size_t)t * (BH / 4) + idx]);
        float4 s;
        mem.x = mem.x * DECAY + v.x; s.x = (mem.x >= THRESH) ? 1.f : 0.f; mem.x -= s.x * THRESH;
        mem.y = mem.y * DECAY + v.y; s.y = (mem.y >= THRESH) ? 1.f : 0.f; mem.y -= s.y * THRESH;
        mem.z = mem.z * DECAY + v.z; s.z = (mem.z >= THRESH) ? 1.f : 0.f; mem.z -= s.z * THRESH;
        mem.w = mem.w * DECAY + v.w; s.w = (mem.w >= THRESH) ? 1.f : 0.f; mem.w -= s.w * THRESH;
        out[(size_t)t * (BH / 4) + idx] = s;
        if (s.x + s.y + s.z + s.w > 0.f) {     // rare (~1900 spikes total)
            float sv[4] = {s.x, s.y, s.z, s.w};
            float* u2 = g_U2 + (size_t)(t * BATCH + b) * OUT_DIM;
#pragma unroll
            for (int q = 0; q < 4; q++) {
                if (sv[q] != 0.f) {
                    const float* w = W2 + (h0 + q) * OUT_DIM;
#pragma unroll
                    for (int o = 0; o < OUT_DIM; o++) atomicAdd(&u2[o], w[o]);
                }
            }
        }
    }
}

// ------------------------- scan2: smem-staged LIF output ------------------
// 20 blocks x 128 threads; block stages its [100][128] U2 slice into smem
// with fully parallel coalesced loads, then scans. Each thread reads only
// its own smem writes -> no barrier needed.
__global__ void scan2_kernel(float* __restrict__ out2) {
    extern __shared__ float sm[];                 // [100][128]
    const int tid = threadIdx.x;
    const int lane0 = blockIdx.x * 128;
#pragma unroll 10
    for (int t = 0; t < T_STEPS; t++)
        sm[t * 128 + tid] = g_U2[(size_t)t * BO + lane0 + tid];
    float mem = 0.0f;
#pragma unroll 5
    for (int t = 0; t < T_STEPS; t++) {
        float u = sm[t * 128 + tid];
        mem = mem * DECAY + u;
        float s = (mem >= THRESH) ? 1.0f : 0.0f;
        mem -= s * THRESH;
        out2[(size_t)t * BO + lane0 + tid] = s;
    }
}

// ------------------------- launch ------------------------------------------
extern "C" void kernel_launch(void* const* d_in, const int* in_sizes, int n_in,
                              void* d_out, int out_size) {
    const float* X  = (const float*)d_in[0];
    const float* W1 = (const float*)d_in[1];
    const float* W2 = (const float*)d_in[2];
    float* out = (float*)d_out;
    (void)in_sizes; (void)n_in; (void)out_size;

    static bool attr_done = false;
    if (!attr_done) {
        cudaFuncSetAttribute(gemm1_kernel, cudaFuncAttributeMaxDynamicSharedMemorySize, SMEM_TOTAL);
        cudaFuncSetAttribute(scan2_kernel, cudaFuncAttributeMaxDynamicSharedMemorySize, 51200);
        attr_done = true;
    }

    prep_kernel<<<PREPX_BLKS + PREPW_BLKS + ZERO_BLKS, 256>>>(X, W1);

    gemm1_kernel<<<dim3(8, 200), 256, SMEM_TOTAL>>>();

    scan1_kernel<<<128, 512>>>((float4*)out, W2);

    scan2_kernel<<<20, 128, 51200>>>(out + HID_OUT);
}